// round 1
// baseline (speedup 1.0000x reference)
#include <cuda_runtime.h>
#include <cuda_bf16.h>
#include <math.h>

#define N_NODES 100000
#define N_EDGES 1000000
#define FEAT 64
#define N_GRAPHS 512
#define N_CLS 10
#define BN_EPS 1e-5f

// Scratch (device globals — no allocation allowed)
__device__ float g_agg[N_NODES * FEAT];
__device__ float g_h1[N_NODES * FEAT];
__device__ float g_h2[N_NODES * FEAT];
__device__ float g_sums[N_GRAPHS * FEAT];
__device__ float g_cnts[N_GRAPHS];

// ---------------------------------------------------------------------------
// Scatter-add: agg[dst] += h[src], vectorized red.global.add.v4.f32
// 16 threads per edge, each handles one float4 chunk (coalesced 256B gather).
// ---------------------------------------------------------------------------
__global__ __launch_bounds__(256) void scatter_kernel(
    const float* __restrict__ h,
    const int* __restrict__ src,
    const int* __restrict__ dst,
    float* __restrict__ agg)
{
    long long tid = (long long)blockIdx.x * blockDim.x + threadIdx.x;
    int e = (int)(tid >> 4);
    int c = (int)(tid & 15);
    if (e >= N_EDGES) return;
    int s = __ldg(src + e);
    int d = __ldg(dst + e);
    const float4* p = reinterpret_cast<const float4*>(h + (size_t)s * FEAT) + c;
    float4 v = __ldg(p);
    float* q = agg + (size_t)d * FEAT + c * 4;
    asm volatile("red.global.add.v4.f32 [%0], {%1,%2,%3,%4};"
                 :: "l"(q), "f"(v.x), "f"(v.y), "f"(v.z), "f"(v.w)
                 : "memory");
}

// ---------------------------------------------------------------------------
// Fused GIN MLP: out = [relu?]( relu( bnfold((x+agg) @ wa + ba) ) @ wb + bb )
// BN folded into wa/ba. Weights cached in SMEM, persistent grid.
// 256 threads: 4 nodes/iter, thread (ln = tid>>6, f = tid&63).
// ---------------------------------------------------------------------------
__global__ __launch_bounds__(256) void mlp_kernel(
    const float* __restrict__ xin,
    const float* __restrict__ agg,
    const float* __restrict__ wa, const float* __restrict__ ba,
    const float* __restrict__ gam, const float* __restrict__ bet,
    const float* __restrict__ mu,  const float* __restrict__ var,
    const float* __restrict__ wb,  const float* __restrict__ bb,
    float* __restrict__ out, int relu_out)
{
    __shared__ __align__(16) float wa_s[FEAT * FEAT];
    __shared__ __align__(16) float wb_s[FEAT * FEAT];
    __shared__ float b0_s[FEAT];
    __shared__ float b1_s[FEAT];
    __shared__ float s_s[FEAT];
    __shared__ __align__(16) float t_s[4 * FEAT];
    __shared__ __align__(16) float u_s[4 * FEAT];

    int tid = threadIdx.x;
    int f = tid & 63;
    int ln = tid >> 6;

    if (tid < FEAT) {
        float s = gam[tid] * rsqrtf(var[tid] + BN_EPS);
        s_s[tid] = s;
        b0_s[tid] = (ba[tid] - mu[tid]) * s + bet[tid];
        b1_s[tid] = bb[tid];
    }
    __syncthreads();
    for (int i = tid; i < FEAT * FEAT; i += 256) {
        int col = i & 63;
        wa_s[i] = wa[i] * s_s[col];
        wb_s[i] = wb[i];
    }
    __syncthreads();

    for (int base = blockIdx.x * 4; base < N_NODES; base += gridDim.x * 4) {
        int node = base + ln;
        if (node < N_NODES) {
            t_s[ln * FEAT + f] = xin[(size_t)node * FEAT + f] + agg[(size_t)node * FEAT + f];
        }
        __syncthreads();

        float acc = b0_s[f];
        const float4* t4 = reinterpret_cast<const float4*>(t_s + ln * FEAT);
#pragma unroll
        for (int kq = 0; kq < 16; kq++) {
            float4 tv = t4[kq];
            int k = kq * 4;
            acc = fmaf(tv.x, wa_s[(k + 0) * FEAT + f], acc);
            acc = fmaf(tv.y, wa_s[(k + 1) * FEAT + f], acc);
            acc = fmaf(tv.z, wa_s[(k + 2) * FEAT + f], acc);
            acc = fmaf(tv.w, wa_s[(k + 3) * FEAT + f], acc);
        }
        acc = fmaxf(acc, 0.0f);
        u_s[ln * FEAT + f] = acc;
        __syncthreads();

        float acc2 = b1_s[f];
        const float4* u4 = reinterpret_cast<const float4*>(u_s + ln * FEAT);
#pragma unroll
        for (int kq = 0; kq < 16; kq++) {
            float4 uv = u4[kq];
            int k = kq * 4;
            acc2 = fmaf(uv.x, wb_s[(k + 0) * FEAT + f], acc2);
            acc2 = fmaf(uv.y, wb_s[(k + 1) * FEAT + f], acc2);
            acc2 = fmaf(uv.z, wb_s[(k + 2) * FEAT + f], acc2);
            acc2 = fmaf(uv.w, wb_s[(k + 3) * FEAT + f], acc2);
        }
        if (relu_out) acc2 = fmaxf(acc2, 0.0f);
        if (node < N_NODES) out[(size_t)node * FEAT + f] = acc2;
        __syncthreads();
    }
}

// ---------------------------------------------------------------------------
// Global mean pool, phase 1: per-graph sums + counts via vector reds
// ---------------------------------------------------------------------------
__global__ __launch_bounds__(256) void pool_kernel(
    const float* __restrict__ h,
    const int* __restrict__ batch,
    float* __restrict__ sums,
    float* __restrict__ cnts)
{
    long long tid = (long long)blockIdx.x * blockDim.x + threadIdx.x;
    int node = (int)(tid >> 4);
    int c = (int)(tid & 15);
    if (node >= N_NODES) return;
    int b = __ldg(batch + node);
    const float4* p = reinterpret_cast<const float4*>(h + (size_t)node * FEAT) + c;
    float4 v = __ldg(p);
    float* q = sums + (size_t)b * FEAT + c * 4;
    asm volatile("red.global.add.v4.f32 [%0], {%1,%2,%3,%4};"
                 :: "l"(q), "f"(v.x), "f"(v.y), "f"(v.z), "f"(v.w)
                 : "memory");
    if (c == 0) atomicAdd(cnts + b, 1.0f);
}

// ---------------------------------------------------------------------------
// Classifier: out[g][c] = (sums[g]/cnt[g]) @ wc + bc    (wc is [64,10])
// ---------------------------------------------------------------------------
__global__ __launch_bounds__(64) void classify_kernel(
    const float* __restrict__ sums,
    const float* __restrict__ cnts,
    const float* __restrict__ wc,
    const float* __restrict__ bc,
    float* __restrict__ out)
{
    int g = blockIdx.x;
    int tid = threadIdx.x;
    __shared__ float p[FEAT];
    float cnt = fmaxf(__ldg(cnts + g), 1.0f);
    p[tid] = sums[(size_t)g * FEAT + tid] / cnt;
    __syncthreads();
    if (tid < N_CLS) {
        float acc = bc[tid];
#pragma unroll
        for (int k = 0; k < FEAT; k++) {
            acc = fmaf(p[k], wc[k * N_CLS + tid], acc);
        }
        out[(size_t)g * N_CLS + tid] = acc;
    }
}

// ---------------------------------------------------------------------------
extern "C" void kernel_launch(void* const* d_in, const int* in_sizes, int n_in,
                              void* d_out, int out_size)
{
    const float* x   = (const float*)d_in[0];
    const int*   ei  = (const int*)d_in[1];
    const int*   bat = (const int*)d_in[2];
    const float* w0a = (const float*)d_in[3];
    const float* b0a = (const float*)d_in[4];
    const float* g0  = (const float*)d_in[5];
    const float* be0 = (const float*)d_in[6];
    const float* m0  = (const float*)d_in[7];
    const float* v0  = (const float*)d_in[8];
    const float* w0b = (const float*)d_in[9];
    const float* b0b = (const float*)d_in[10];
    const float* w1a = (const float*)d_in[11];
    const float* b1a = (const float*)d_in[12];
    const float* g1  = (const float*)d_in[13];
    const float* be1 = (const float*)d_in[14];
    const float* m1  = (const float*)d_in[15];
    const float* v1  = (const float*)d_in[16];
    const float* w1b = (const float*)d_in[17];
    const float* b1b = (const float*)d_in[18];
    const float* wc  = (const float*)d_in[19];
    const float* bc  = (const float*)d_in[20];
    float* out = (float*)d_out;

    const int* src = ei;            // edge_index[0]
    const int* dst = ei + N_EDGES;  // edge_index[1]

    float *p_agg, *p_h1, *p_h2, *p_sums, *p_cnts;
    cudaGetSymbolAddress((void**)&p_agg,  g_agg);
    cudaGetSymbolAddress((void**)&p_h1,   g_h1);
    cudaGetSymbolAddress((void**)&p_h2,   g_h2);
    cudaGetSymbolAddress((void**)&p_sums, g_sums);
    cudaGetSymbolAddress((void**)&p_cnts, g_cnts);

    const int scatter_blocks = (N_EDGES * 16) / 256;       // 62500
    const int mlp_blocks = 888;                            // persistent-ish
    const int pool_blocks = (N_NODES * 16 + 255) / 256;    // 6250

    // ---- Conv 0 ----
    cudaMemsetAsync(p_agg, 0, (size_t)N_NODES * FEAT * sizeof(float));
    scatter_kernel<<<scatter_blocks, 256>>>(x, src, dst, p_agg);
    mlp_kernel<<<mlp_blocks, 256>>>(x, p_agg, w0a, b0a, g0, be0, m0, v0,
                                    w0b, b0b, p_h1, /*relu_out=*/1);

    // ---- Conv 1 ----
    cudaMemsetAsync(p_agg, 0, (size_t)N_NODES * FEAT * sizeof(float));
    scatter_kernel<<<scatter_blocks, 256>>>(p_h1, src, dst, p_agg);
    mlp_kernel<<<mlp_blocks, 256>>>(p_h1, p_agg, w1a, b1a, g1, be1, m1, v1,
                                    w1b, b1b, p_h2, /*relu_out=*/0);

    // ---- Pool + classify ----
    cudaMemsetAsync(p_sums, 0, (size_t)N_GRAPHS * FEAT * sizeof(float));
    cudaMemsetAsync(p_cnts, 0, (size_t)N_GRAPHS * sizeof(float));
    pool_kernel<<<pool_blocks, 256>>>(p_h2, bat, p_sums, p_cnts);
    classify_kernel<<<N_GRAPHS, 64>>>(p_sums, p_cnts, wc, bc, out);
}

// round 2
// speedup vs baseline: 1.5129x; 1.5129x over previous
#include <cuda_runtime.h>
#include <cuda_bf16.h>
#include <math.h>

#define N_NODES 100000
#define N_EDGES 1000000
#define FEAT 64
#define N_GRAPHS 512
#define N_CLS 10
#define BN_EPS 1e-5f

// Scratch (device globals — no allocation allowed)
__device__ float g_agg[N_NODES * FEAT];
__device__ float g_h1[N_NODES * FEAT];
__device__ float g_sums[N_GRAPHS * FEAT];
__device__ float g_cnts[N_GRAPHS];

// ---------------------------------------------------------------------------
// Scatter-add: agg[dst] += h[src], vectorized red.global.add.v4.f32
// ---------------------------------------------------------------------------
__global__ __launch_bounds__(256) void scatter_kernel(
    const float* __restrict__ h,
    const int* __restrict__ src,
    const int* __restrict__ dst,
    float* __restrict__ agg)
{
    long long tid = (long long)blockIdx.x * blockDim.x + threadIdx.x;
    int e = (int)(tid >> 4);
    int c = (int)(tid & 15);
    if (e >= N_EDGES) return;
    int s = __ldg(src + e);
    int d = __ldg(dst + e);
    const float4* p = reinterpret_cast<const float4*>(h + (size_t)s * FEAT) + c;
    float4 v = __ldg(p);
    float* q = agg + (size_t)d * FEAT + c * 4;
    asm volatile("red.global.add.v4.f32 [%0], {%1,%2,%3,%4};"
                 :: "l"(q), "f"(v.x), "f"(v.y), "f"(v.z), "f"(v.w)
                 : "memory");
}

// ---------------------------------------------------------------------------
// Graph-size counts (batch is the only input needed)
// ---------------------------------------------------------------------------
__global__ __launch_bounds__(256) void count_kernel(
    const int* __restrict__ batch, float* __restrict__ cnts)
{
    int i = blockIdx.x * blockDim.x + threadIdx.x;
    if (i < N_NODES) atomicAdd(cnts + __ldg(batch + i), 1.0f);
}

// ---------------------------------------------------------------------------
// Fused GIN MLP, register-resident node-per-thread GEMM.
// mode 0: out[node] = relu( mlp(x+agg) )         (conv0)
// mode 1: red-add    mlp(x+agg) into sums[batch] (conv1 + fused mean-pool sum)
// Inner loop: 1 broadcast LDS.128 (4 weight cols) : 4 FMA.
// ---------------------------------------------------------------------------
#define U_STRIDE 68   // padded row stride (floats): lanes map to 8 bank-groups

__global__ __launch_bounds__(128) void mlp_kernel(
    const float* __restrict__ xin,
    const float* __restrict__ agg,
    const float* __restrict__ wa, const float* __restrict__ ba,
    const float* __restrict__ gam, const float* __restrict__ bet,
    const float* __restrict__ mu,  const float* __restrict__ var,
    const float* __restrict__ wb,  const float* __restrict__ bb,
    float* __restrict__ out,
    const int* __restrict__ batch, float* __restrict__ sums,
    int mode)
{
    __shared__ __align__(16) float wa_s[FEAT * FEAT];
    __shared__ __align__(16) float wb_s[FEAT * FEAT];
    __shared__ __align__(16) float b0_s[FEAT];
    __shared__ __align__(16) float b1_s[FEAT];
    __shared__ float s_s[FEAT];
    __shared__ __align__(16) float u_s[128 * U_STRIDE];

    int tid = threadIdx.x;

    if (tid < FEAT) {
        float s = gam[tid] * rsqrtf(var[tid] + BN_EPS);
        s_s[tid] = s;
        b0_s[tid] = (ba[tid] - mu[tid]) * s + bet[tid];
        b1_s[tid] = bb[tid];
    }
    __syncthreads();
    for (int i = tid; i < FEAT * FEAT; i += 128) {
        int col = i & 63;
        wa_s[i] = wa[i] * s_s[col];
        wb_s[i] = wb[i];
    }
    __syncthreads();

    int node = blockIdx.x * 128 + tid;
    bool valid = node < N_NODES;

    // Load t = x + agg into registers (64 floats)
    float t[FEAT];
    if (valid) {
        const float4* xp = reinterpret_cast<const float4*>(xin + (size_t)node * FEAT);
        const float4* ap = reinterpret_cast<const float4*>(agg + (size_t)node * FEAT);
#pragma unroll
        for (int q = 0; q < 16; q++) {
            float4 a = __ldg(xp + q);
            float4 b = __ldg(ap + q);
            t[4 * q + 0] = a.x + b.x;
            t[4 * q + 1] = a.y + b.y;
            t[4 * q + 2] = a.z + b.z;
            t[4 * q + 3] = a.w + b.w;
        }
    } else {
#pragma unroll
        for (int k = 0; k < FEAT; k++) t[k] = 0.0f;
    }

    // ---- Layer 1: u = relu(t @ wa + b0), stash u in private SMEM row ----
    float* urow = u_s + tid * U_STRIDE;
    const float4* b0v = reinterpret_cast<const float4*>(b0_s);
    for (int fq = 0; fq < 16; fq++) {
        float4 acc = b0v[fq];
#pragma unroll
        for (int k = 0; k < FEAT; k++) {
            float4 w = *reinterpret_cast<const float4*>(wa_s + k * FEAT + fq * 4);
            acc.x = fmaf(t[k], w.x, acc.x);
            acc.y = fmaf(t[k], w.y, acc.y);
            acc.z = fmaf(t[k], w.z, acc.z);
            acc.w = fmaf(t[k], w.w, acc.w);
        }
        acc.x = fmaxf(acc.x, 0.0f);
        acc.y = fmaxf(acc.y, 0.0f);
        acc.z = fmaxf(acc.z, 0.0f);
        acc.w = fmaxf(acc.w, 0.0f);
        *reinterpret_cast<float4*>(urow + fq * 4) = acc;
    }

    // reload u into t registers (private row, no cross-thread sharing → no sync)
#pragma unroll
    for (int q = 0; q < 16; q++) {
        float4 u = *reinterpret_cast<const float4*>(urow + q * 4);
        t[4 * q + 0] = u.x;
        t[4 * q + 1] = u.y;
        t[4 * q + 2] = u.z;
        t[4 * q + 3] = u.w;
    }

    // ---- Layer 2: y = t @ wb + b1 ----
    int b = 0;
    if (mode == 1 && valid) b = __ldg(batch + node);
    const float4* b1v = reinterpret_cast<const float4*>(b1_s);
    for (int fq = 0; fq < 16; fq++) {
        float4 acc = b1v[fq];
#pragma unroll
        for (int k = 0; k < FEAT; k++) {
            float4 w = *reinterpret_cast<const float4*>(wb_s + k * FEAT + fq * 4);
            acc.x = fmaf(t[k], w.x, acc.x);
            acc.y = fmaf(t[k], w.y, acc.y);
            acc.z = fmaf(t[k], w.z, acc.z);
            acc.w = fmaf(t[k], w.w, acc.w);
        }
        if (!valid) continue;
        if (mode == 0) {
            // conv0: relu then store h1
            acc.x = fmaxf(acc.x, 0.0f);
            acc.y = fmaxf(acc.y, 0.0f);
            acc.z = fmaxf(acc.z, 0.0f);
            acc.w = fmaxf(acc.w, 0.0f);
            *reinterpret_cast<float4*>(out + (size_t)node * FEAT + fq * 4) = acc;
        } else {
            // conv1: red directly into per-graph sums (fused mean-pool numerator)
            float* q = sums + (size_t)b * FEAT + fq * 4;
            asm volatile("red.global.add.v4.f32 [%0], {%1,%2,%3,%4};"
                         :: "l"(q), "f"(acc.x), "f"(acc.y), "f"(acc.z), "f"(acc.w)
                         : "memory");
        }
    }
}

// ---------------------------------------------------------------------------
// Classifier: out[g][c] = (sums[g]/cnt[g]) @ wc + bc    (wc is [64,10])
// ---------------------------------------------------------------------------
__global__ __launch_bounds__(64) void classify_kernel(
    const float* __restrict__ sums,
    const float* __restrict__ cnts,
    const float* __restrict__ wc,
    const float* __restrict__ bc,
    float* __restrict__ out)
{
    int g = blockIdx.x;
    int tid = threadIdx.x;
    __shared__ float p[FEAT];
    float cnt = fmaxf(__ldg(cnts + g), 1.0f);
    p[tid] = sums[(size_t)g * FEAT + tid] / cnt;
    __syncthreads();
    if (tid < N_CLS) {
        float acc = bc[tid];
#pragma unroll
        for (int k = 0; k < FEAT; k++) {
            acc = fmaf(p[k], wc[k * N_CLS + tid], acc);
        }
        out[(size_t)g * N_CLS + tid] = acc;
    }
}

// ---------------------------------------------------------------------------
extern "C" void kernel_launch(void* const* d_in, const int* in_sizes, int n_in,
                              void* d_out, int out_size)
{
    const float* x   = (const float*)d_in[0];
    const int*   ei  = (const int*)d_in[1];
    const int*   bat = (const int*)d_in[2];
    const float* w0a = (const float*)d_in[3];
    const float* b0a = (const float*)d_in[4];
    const float* g0  = (const float*)d_in[5];
    const float* be0 = (const float*)d_in[6];
    const float* m0  = (const float*)d_in[7];
    const float* v0  = (const float*)d_in[8];
    const float* w0b = (const float*)d_in[9];
    const float* b0b = (const float*)d_in[10];
    const float* w1a = (const float*)d_in[11];
    const float* b1a = (const float*)d_in[12];
    const float* g1  = (const float*)d_in[13];
    const float* be1 = (const float*)d_in[14];
    const float* m1  = (const float*)d_in[15];
    const float* v1  = (const float*)d_in[16];
    const float* w1b = (const float*)d_in[17];
    const float* b1b = (const float*)d_in[18];
    const float* wc  = (const float*)d_in[19];
    const float* bc  = (const float*)d_in[20];
    float* out = (float*)d_out;

    const int* src = ei;            // edge_index[0]
    const int* dst = ei + N_EDGES;  // edge_index[1]

    float *p_agg, *p_h1, *p_sums, *p_cnts;
    cudaGetSymbolAddress((void**)&p_agg,  g_agg);
    cudaGetSymbolAddress((void**)&p_h1,   g_h1);
    cudaGetSymbolAddress((void**)&p_sums, g_sums);
    cudaGetSymbolAddress((void**)&p_cnts, g_cnts);

    const int scatter_blocks = (N_EDGES * 16) / 256;       // 62500
    const int mlp_blocks = (N_NODES + 127) / 128;          // 782
    const int node_blocks = (N_NODES + 255) / 256;         // 391

    // Up-front zeroing + counts (independent of conv pipeline)
    cudaMemsetAsync(p_sums, 0, (size_t)N_GRAPHS * FEAT * sizeof(float));
    cudaMemsetAsync(p_cnts, 0, (size_t)N_GRAPHS * sizeof(float));
    count_kernel<<<node_blocks, 256>>>(bat, p_cnts);

    // ---- Conv 0 ----
    cudaMemsetAsync(p_agg, 0, (size_t)N_NODES * FEAT * sizeof(float));
    scatter_kernel<<<scatter_blocks, 256>>>(x, src, dst, p_agg);
    mlp_kernel<<<mlp_blocks, 128>>>(x, p_agg, w0a, b0a, g0, be0, m0, v0,
                                    w0b, b0b, p_h1, bat, p_sums, /*mode=*/0);

    // ---- Conv 1 (mean-pool sum fused into the MLP epilogue) ----
    cudaMemsetAsync(p_agg, 0, (size_t)N_NODES * FEAT * sizeof(float));
    scatter_kernel<<<scatter_blocks, 256>>>(p_h1, src, dst, p_agg);
    mlp_kernel<<<mlp_blocks, 128>>>(p_h1, p_agg, w1a, b1a, g1, be1, m1, v1,
                                    w1b, b1b, /*out unused*/ p_h1, bat, p_sums, /*mode=*/1);

    // ---- Classify ----
    classify_kernel<<<N_GRAPHS, 64>>>(p_sums, p_cnts, wc, bc, out);
}

// round 3
// speedup vs baseline: 1.5229x; 1.0066x over previous
#include <cuda_runtime.h>
#include <cuda_bf16.h>
#include <math.h>

#define N_NODES 100000
#define N_EDGES 1000000
#define FEAT 64
#define N_GRAPHS 512
#define N_CLS 10
#define BN_EPS 1e-5f

// Scratch (device globals — no allocation allowed)
__device__ float g_agg[N_NODES * FEAT];
__device__ float g_h1[N_NODES * FEAT];
__device__ float g_sums[N_GRAPHS * FEAT];
__device__ float g_cnts[N_GRAPHS];

// ---------------------------------------------------------------------------
// Scatter-add: agg[dst] += h[src]. 16 threads per edge, 2 edges per thread
// (independent gathers in flight -> higher issue rate).
// ---------------------------------------------------------------------------
__global__ __launch_bounds__(256) void scatter_kernel(
    const float* __restrict__ h,
    const int* __restrict__ src,
    const int* __restrict__ dst,
    float* __restrict__ agg)
{
    long long tid = (long long)blockIdx.x * blockDim.x + threadIdx.x;
    int c = (int)(tid & 15);
    int e0 = (int)(tid >> 4) * 2;
    if (e0 >= N_EDGES) return;
    int e1 = e0 + 1;  // N_EDGES is even -> always valid when e0 is

    int s0 = __ldg(src + e0);
    int d0 = __ldg(dst + e0);
    int s1 = __ldg(src + e1);
    int d1 = __ldg(dst + e1);

    float4 v0 = __ldg(reinterpret_cast<const float4*>(h + (size_t)s0 * FEAT) + c);
    float4 v1 = __ldg(reinterpret_cast<const float4*>(h + (size_t)s1 * FEAT) + c);

    float* q0 = agg + (size_t)d0 * FEAT + c * 4;
    float* q1 = agg + (size_t)d1 * FEAT + c * 4;
    asm volatile("red.global.add.v4.f32 [%0], {%1,%2,%3,%4};"
                 :: "l"(q0), "f"(v0.x), "f"(v0.y), "f"(v0.z), "f"(v0.w) : "memory");
    asm volatile("red.global.add.v4.f32 [%0], {%1,%2,%3,%4};"
                 :: "l"(q1), "f"(v1.x), "f"(v1.y), "f"(v1.z), "f"(v1.w) : "memory");
}

// ---------------------------------------------------------------------------
// Graph-size counts
// ---------------------------------------------------------------------------
__global__ __launch_bounds__(256) void count_kernel(
    const int* __restrict__ batch, float* __restrict__ cnts)
{
    int i = blockIdx.x * blockDim.x + threadIdx.x;
    if (i < N_NODES) atomicAdd(cnts + __ldg(batch + i), 1.0f);
}

// ---------------------------------------------------------------------------
// Fused GIN MLP, fully register-resident node-per-thread GEMM.
// mode 0: out[node] = relu( mlp(x+agg) )         (conv0)
// mode 1: red-add    mlp(x+agg) into sums[batch] (conv1 + fused mean-pool sum)
// Inner loop: 1 broadcast LDS.128 (4 weight cols) : 4 FMA. No SMEM roundtrip.
// ---------------------------------------------------------------------------
__global__ __launch_bounds__(128) void mlp_kernel(
    const float* __restrict__ xin,
    const float* __restrict__ agg,
    const float* __restrict__ wa, const float* __restrict__ ba,
    const float* __restrict__ gam, const float* __restrict__ bet,
    const float* __restrict__ mu,  const float* __restrict__ var,
    const float* __restrict__ wb,  const float* __restrict__ bb,
    float* __restrict__ out,
    const int* __restrict__ batch, float* __restrict__ sums,
    int mode)
{
    __shared__ __align__(16) float wa_s[FEAT * FEAT];
    __shared__ __align__(16) float wb_s[FEAT * FEAT];
    __shared__ __align__(16) float b0_s[FEAT];
    __shared__ __align__(16) float b1_s[FEAT];
    __shared__ float s_s[FEAT];

    int tid = threadIdx.x;

    if (tid < FEAT) {
        float s = gam[tid] * rsqrtf(var[tid] + BN_EPS);
        s_s[tid] = s;
        b0_s[tid] = (ba[tid] - mu[tid]) * s + bet[tid];
        b1_s[tid] = bb[tid];
    }
    __syncthreads();
    for (int i = tid; i < FEAT * FEAT; i += 128) {
        int col = i & 63;
        wa_s[i] = wa[i] * s_s[col];
        wb_s[i] = wb[i];
    }
    __syncthreads();

    int node = blockIdx.x * 128 + tid;
    bool valid = node < N_NODES;

    // t = x + agg (registers)
    float t[FEAT];
    if (valid) {
        const float4* xp = reinterpret_cast<const float4*>(xin + (size_t)node * FEAT);
        const float4* ap = reinterpret_cast<const float4*>(agg + (size_t)node * FEAT);
#pragma unroll
        for (int q = 0; q < 16; q++) {
            float4 a = __ldg(xp + q);
            float4 b = __ldg(ap + q);
            t[4 * q + 0] = a.x + b.x;
            t[4 * q + 1] = a.y + b.y;
            t[4 * q + 2] = a.z + b.z;
            t[4 * q + 3] = a.w + b.w;
        }
    } else {
#pragma unroll
        for (int k = 0; k < FEAT; k++) t[k] = 0.0f;
    }

    // ---- Layer 1: u = relu(t @ wa + b0), u stays in registers ----
    float u[FEAT];
    const float4* b0v = reinterpret_cast<const float4*>(b0_s);
#pragma unroll
    for (int fq = 0; fq < 16; fq++) {
        float4 acc = b0v[fq];
#pragma unroll
        for (int k = 0; k < FEAT; k++) {
            float4 w = *reinterpret_cast<const float4*>(wa_s + k * FEAT + fq * 4);
            acc.x = fmaf(t[k], w.x, acc.x);
            acc.y = fmaf(t[k], w.y, acc.y);
            acc.z = fmaf(t[k], w.z, acc.z);
            acc.w = fmaf(t[k], w.w, acc.w);
        }
        u[4 * fq + 0] = fmaxf(acc.x, 0.0f);
        u[4 * fq + 1] = fmaxf(acc.y, 0.0f);
        u[4 * fq + 2] = fmaxf(acc.z, 0.0f);
        u[4 * fq + 3] = fmaxf(acc.w, 0.0f);
    }

    // ---- Layer 2: y = u @ wb + b1 ----
    int b = 0;
    if (mode == 1 && valid) b = __ldg(batch + node);
    const float4* b1v = reinterpret_cast<const float4*>(b1_s);
#pragma unroll
    for (int fq = 0; fq < 16; fq++) {
        float4 acc = b1v[fq];
#pragma unroll
        for (int k = 0; k < FEAT; k++) {
            float4 w = *reinterpret_cast<const float4*>(wb_s + k * FEAT + fq * 4);
            acc.x = fmaf(u[k], w.x, acc.x);
            acc.y = fmaf(u[k], w.y, acc.y);
            acc.z = fmaf(u[k], w.z, acc.z);
            acc.w = fmaf(u[k], w.w, acc.w);
        }
        if (!valid) continue;
        if (mode == 0) {
            acc.x = fmaxf(acc.x, 0.0f);
            acc.y = fmaxf(acc.y, 0.0f);
            acc.z = fmaxf(acc.z, 0.0f);
            acc.w = fmaxf(acc.w, 0.0f);
            *reinterpret_cast<float4*>(out + (size_t)node * FEAT + fq * 4) = acc;
        } else {
            float* q = sums + (size_t)b * FEAT + fq * 4;
            asm volatile("red.global.add.v4.f32 [%0], {%1,%2,%3,%4};"
                         :: "l"(q), "f"(acc.x), "f"(acc.y), "f"(acc.z), "f"(acc.w)
                         : "memory");
        }
    }
}

// ---------------------------------------------------------------------------
// Classifier: out[g][c] = (sums[g]/cnt[g]) @ wc + bc    (wc is [64,10])
// ---------------------------------------------------------------------------
__global__ __launch_bounds__(64) void classify_kernel(
    const float* __restrict__ sums,
    const float* __restrict__ cnts,
    const float* __restrict__ wc,
    const float* __restrict__ bc,
    float* __restrict__ out)
{
    int g = blockIdx.x;
    int tid = threadIdx.x;
    __shared__ float p[FEAT];
    float cnt = fmaxf(__ldg(cnts + g), 1.0f);
    p[tid] = sums[(size_t)g * FEAT + tid] / cnt;
    __syncthreads();
    if (tid < N_CLS) {
        float acc = bc[tid];
#pragma unroll
        for (int k = 0; k < FEAT; k++) {
            acc = fmaf(p[k], wc[k * N_CLS + tid], acc);
        }
        out[(size_t)g * N_CLS + tid] = acc;
    }
}

// ---------------------------------------------------------------------------
extern "C" void kernel_launch(void* const* d_in, const int* in_sizes, int n_in,
                              void* d_out, int out_size)
{
    const float* x   = (const float*)d_in[0];
    const int*   ei  = (const int*)d_in[1];
    const int*   bat = (const int*)d_in[2];
    const float* w0a = (const float*)d_in[3];
    const float* b0a = (const float*)d_in[4];
    const float* g0  = (const float*)d_in[5];
    const float* be0 = (const float*)d_in[6];
    const float* m0  = (const float*)d_in[7];
    const float* v0  = (const float*)d_in[8];
    const float* w0b = (const float*)d_in[9];
    const float* b0b = (const float*)d_in[10];
    const float* w1a = (const float*)d_in[11];
    const float* b1a = (const float*)d_in[12];
    const float* g1  = (const float*)d_in[13];
    const float* be1 = (const float*)d_in[14];
    const float* m1  = (const float*)d_in[15];
    const float* v1  = (const float*)d_in[16];
    const float* w1b = (const float*)d_in[17];
    const float* b1b = (const float*)d_in[18];
    const float* wc  = (const float*)d_in[19];
    const float* bc  = (const float*)d_in[20];
    float* out = (float*)d_out;

    const int* src = ei;            // edge_index[0]
    const int* dst = ei + N_EDGES;  // edge_index[1]

    float *p_agg, *p_h1, *p_sums, *p_cnts;
    cudaGetSymbolAddress((void**)&p_agg,  g_agg);
    cudaGetSymbolAddress((void**)&p_h1,   g_h1);
    cudaGetSymbolAddress((void**)&p_sums, g_sums);
    cudaGetSymbolAddress((void**)&p_cnts, g_cnts);

    const int scatter_blocks = (N_EDGES / 2 * 16) / 256;   // 31250
    const int mlp_blocks = (N_NODES + 127) / 128;          // 782
    const int node_blocks = (N_NODES + 255) / 256;         // 391

    // Up-front zeroing + counts (independent of conv pipeline)
    cudaMemsetAsync(p_sums, 0, (size_t)N_GRAPHS * FEAT * sizeof(float));
    cudaMemsetAsync(p_cnts, 0, (size_t)N_GRAPHS * sizeof(float));
    count_kernel<<<node_blocks, 256>>>(bat, p_cnts);

    // ---- Conv 0 ----
    cudaMemsetAsync(p_agg, 0, (size_t)N_NODES * FEAT * sizeof(float));
    scatter_kernel<<<scatter_blocks, 256>>>(x, src, dst, p_agg);
    mlp_kernel<<<mlp_blocks, 128>>>(x, p_agg, w0a, b0a, g0, be0, m0, v0,
                                    w0b, b0b, p_h1, bat, p_sums, /*mode=*/0);

    // ---- Conv 1 (mean-pool sum fused into the MLP epilogue) ----
    cudaMemsetAsync(p_agg, 0, (size_t)N_NODES * FEAT * sizeof(float));
    scatter_kernel<<<scatter_blocks, 256>>>(p_h1, src, dst, p_agg);
    mlp_kernel<<<mlp_blocks, 128>>>(p_h1, p_agg, w1a, b1a, g1, be1, m1, v1,
                                    w1b, b1b, /*out unused*/ p_h1, bat, p_sums, /*mode=*/1);

    // ---- Classify ----
    classify_kernel<<<N_GRAPHS, 64>>>(p_sums, p_cnts, wc, bc, out);
}